// round 10
// baseline (speedup 1.0000x reference)
#include <cuda_runtime.h>
#include <cstdint>

#define GRID1   20
#define NCPAD   8192
#define CAP     16             // bucket capacity (overflow P ~ 2e-12)
#define KC      20             // register candidate cap (P(cnt>20) ~ 1e-9)
#define CSTRIDE 32
#define MAXM    8192
#define MAXN    8192
#define GBLK    148
#define TBLK    64
#define OWNER_INIT 0x7FFFFFFF

typedef unsigned long long u64;

// ---------------- device scratch (no allocations allowed) ----------------
__device__ int            g_cellcnt[NCPAD];          // zero-init; phase D re-zeros
__device__ float4         g_bucket[NCPAD * CAP];     // (x,y,z,bitcast id)
__device__ uint4          g_row[MAXM];               // cnt | first 7 sorted candidates
__device__ unsigned short g_sorted[MAXM * CSTRIDE];  // overflow (pos >= 7)
__device__ int            g_owner[MAXN];             // packed (row<<5 | pos)
__device__ float          g_acc[5];
__device__ volatile unsigned g_bcnt[4];              // zero-init; self-resetting
__device__ volatile unsigned g_bgen[4];              // monotonic generation

__device__ __forceinline__ int cell1(float x) {
    int c = (int)floorf(x * 0.2f);
    return min(max(c, 0), GRID1 - 1);
}

// Generation-based grid barrier; all GBLK blocks co-resident (148 SMs, 1 each).
__device__ __forceinline__ void gsync(int k) {
    __syncthreads();
    if (threadIdx.x == 0) {
        unsigned old = g_bgen[k];
        __threadfence();
        unsigned a = atomicAdd((unsigned*)&g_bcnt[k], 1u);
        if (a == GBLK - 1) {
            g_bcnt[k] = 0;
            __threadfence();
            atomicAdd((unsigned*)&g_bgen[k], 1u);
        } else {
            while (g_bgen[k] == old) { }
        }
    }
    __syncthreads();
    __threadfence();
}

// candidate p of a row given its packed uint4; own=true may use L1 (own writes)
__device__ __forceinline__ int cand_at(uint4 rv, int p, int row, bool own) {
    if (p < 7) {
        unsigned w = (p == 0) ? rv.x : (p < 3) ? rv.y : (p < 5) ? rv.z : rv.w;
        int sh = (p == 0) ? 16 : ((p & 1) ? 0 : 16);
        return (int)((w >> sh) & 0xFFFFu);
    }
    const unsigned short* q = &g_sorted[(size_t)row * CSTRIDE + p];
    return own ? (int)*q : (int)__ldcg(q);
}

__device__ __forceinline__ float sl1(float x) {
    float a = fabsf(x);
    return (a < 1.0f) ? 0.5f * a * a : a - 0.5f;
}

__global__ void __launch_bounds__(TBLK)
fused_kernel(const float* __restrict__ pred, const float* __restrict__ gt,
             int m, int n, float* __restrict__ out) {
    int b = blockIdx.x, tid = threadIdx.x;
    int lane = tid & 31;
    int i = b * TBLK + tid;                 // one pred row AND one gt per thread

    // Hoist pred xyz loads: in flight during phase A + barrier.
    float px = 0.f, py = 0.f, pz = 0.f;
    bool rowv = (i < m);
    if (rowv) {
        px = __ldg(&pred[i * 7 + 0]);
        py = __ldg(&pred[i * 7 + 1]);
        pz = __ldg(&pred[i * 7 + 2]);
    }

    // ========== phase A: bucket build + owner/acc init (fully parallel) ====
    float gx = 0.f, gy = 0.f, gz = 0.f;
    if (i < 5) g_acc[i] = 0.0f;
    if (i < n) {
        g_owner[i] = OWNER_INIT;
        const float* g = gt + (size_t)i * 7;
        gx = __ldg(g); gy = __ldg(g + 1); gz = __ldg(g + 2);
        int c = (cell1(gz) * GRID1 + cell1(gy)) * GRID1 + cell1(gx);
        int slot = atomicAdd(&g_cellcnt[c], 1);
        if (slot < CAP)
            g_bucket[c * CAP + slot] = make_float4(gx, gy, gz, __int_as_float(i));
    }
    gsync(0);

    // ========== phase B: query, z-plane batched, register min-sweep ========
    // Per-dim neighborhood [cell1(px-5), cell1(px+5)] spans <=3 consecutive
    // cells and is a superset (monotone f32 ops); exact dsq<25 test ->
    // identical candidate set to brute force. Entry0 loads are speculative
    // (clamped in-bounds; used only when count>0). a[] holds the KC smallest
    // keys (fbits(dsq)<<32 | j) in ascending order via fully-unrolled
    // register min-sweep == exact serial-argmin order (rounds 1-9).
    uint4 rv = make_uint4(0, 0, 0, 0);
    int   cnt = 0;
    if (rowv) {
        u64 a[KC];
        #pragma unroll
        for (int k = 0; k < KC; ++k) a[k] = ~0ull;
        int x0 = cell1(px - 5.0f), x1 = cell1(px + 5.0f);
        int y0 = cell1(py - 5.0f), y1 = cell1(py + 5.0f);
        int z0 = cell1(pz - 5.0f), z1 = cell1(pz + 5.0f);

        for (int zz = z0; zz <= z1; ++zz) {
            int    cc[9], ci[9];
            float4 v0[9];
            // wave: 9 count loads + 9 speculative entry0 loads (independent)
            #pragma unroll
            for (int dy = 0; dy < 3; ++dy) {
                int yy = y0 + dy;
                #pragma unroll
                for (int dx = 0; dx < 3; ++dx) {
                    int k = dy * 3 + dx;
                    int xx = x0 + dx;
                    bool ok = (yy <= y1) && (xx <= x1);
                    int c = (zz * GRID1 + yy) * GRID1 + xx;
                    c = min(c, NCPAD - 1);           // clamp: always in-bounds
                    ci[k] = c;
                    cc[k] = ok ? __ldg(&g_cellcnt[c]) : 0;
                }
            }
            #pragma unroll
            for (int k = 0; k < 9; ++k) v0[k] = __ldg(&g_bucket[ci[k] * CAP]);

            #pragma unroll
            for (int k = 0; k < 9; ++k) {
                int c2 = min(cc[k], CAP);
                for (int t = 0; t < c2; ++t) {       // c2>1 rare (mean ~1)
                    float4 v = (t == 0) ? v0[k]
                                        : __ldg(&g_bucket[ci[k] * CAP + t]);
                    float dx = px - v.x, dy = py - v.y, dz = pz - v.z;
                    float d = fmaf(dx, dx, fmaf(dy, dy, dz * dz));
                    if (d < 25.0f) {
                        u64 key = ((u64)__float_as_uint(d) << 32)
                                | (unsigned)__float_as_int(v.w);
                        ++cnt;
                        #pragma unroll
                        for (int k2 = 0; k2 < KC; ++k2) {   // register min-sweep
                            u64 mn = min(a[k2], key);
                            key = a[k2] ^ key ^ mn;
                            a[k2] = mn;
                        }
                    }
                }
            }
        }
        cnt = min(cnt, KC);
        unsigned c7[7];
        #pragma unroll
        for (int k = 0; k < 7; ++k)
            c7[k] = (k < cnt) ? (unsigned)(a[k] & 0xFFFFu) : 0u;
        rv.x = (unsigned)cnt | (c7[0] << 16);
        rv.y = c7[1] | (c7[2] << 16);
        rv.z = c7[3] | (c7[4] << 16);
        rv.w = c7[5] | (c7[6] << 16);
        g_row[i] = rv;
        #pragma unroll
        for (int k = 7; k < KC; ++k)
            if (k < cnt)
                g_sorted[(size_t)i * CSTRIDE + k] =
                    (unsigned short)(a[k] & 0xFFFFu);
    }
    __threadfence();   // release g_row/g_sorted before owner atomics

    // ========== phase C: eager-chain greedy matcher (no barriers) ==========
    // owner[j] = min packed (row<<5|pos) ever proposed (atomicMin, monotone).
    // Packed lexicographic order == row priority. On displacement, the winner
    // continues the displaced row's walk (position from the returned value).
    // Fixed point is order-independent == sequential greedy (rounds 3-9).
    if (rowv) {
        int cur = i, p = 0, ccnt = cnt;
        uint4 crv = rv;
        bool own = true;
        while (p < ccnt) {
            int j = cand_at(crv, p, cur, own);
            int my = (cur << 5) | p;
            int old = atomicMin(&g_owner[j], my);
            if (old < my) { ++p; continue; }     // better owner: advance
            if (old == OWNER_INIT) break;        // parked in empty slot: done
            cur = old >> 5;                      // continue displaced row
            p = (old & 31) + 1;
            crv = __ldcg(&g_row[cur]);
            ccnt = (int)(crv.x & 0xFFFFu);
            own = false;
        }
    }
    gsync(1);

    // ========== phase D: gt-side loss (owner[j]>>5 IS the matched row) =====
    // At fixed point each row owns <=1 gt (a parked entry is only replaced by
    // a strictly smaller packed value, which resumes that row's walk past it),
    // so iterating gts enumerates exactly the matched pairs, once each.
    if (i < NCPAD) g_cellcnt[i] = 0;             // zero-state for next replay

    float sc = 0.f, ss = 0.f, so = 0.f, si = 0.f, cf = 0.f;
    if (i < n) {
        int v = __ldcg(&g_owner[i]);             // atomics live in L2
        if (v != OWNER_INIT) {
            int r = v >> 5;                      // matched pred row
            cf = 1.0f;
            const float* pp = pred + (size_t)r * 7;
            const float* gg = gt + (size_t)i * 7;
            float p0 = __ldg(pp),     p1 = __ldg(pp + 1), p2 = __ldg(pp + 2);
            float p3 = __ldg(pp + 3), p4 = __ldg(pp + 4), p5 = __ldg(pp + 5);
            float p6 = __ldg(pp + 6);
            float g3 = __ldg(gg + 3), g4 = __ldg(gg + 4), g5 = __ldg(gg + 5);
            float g6 = __ldg(gg + 6);
            sc = sl1(p0 - gx) + sl1(p1 - gy) + sl1(p2 - gz);
            ss = sl1(p3 - g3) + sl1(p4 - g4) + sl1(p5 - g5);
            float dth = p6 - g6;
            dth = fmaf(-rintf(dth * 0.15915494309f), 6.283185307f, dth);
            so = sl1(dth);                       // sl1(|.|) symmetric: wrap dir irrelevant
            float iw = fminf(p0 + p3 * 0.5f, gx + g3 * 0.5f)
                     - fmaxf(p0 - p3 * 0.5f, gx - g3 * 0.5f);
            iw = fmaxf(iw, 0.0f);
            float ih = fminf(p1 + p4 * 0.5f, gy + g4 * 0.5f)
                     - fmaxf(p1 - p4 * 0.5f, gy - g4 * 0.5f);
            ih = fmaxf(ih, 0.0f);
            float inter = iw * ih;
            float uni = p3 * p4 + g3 * g4 - inter;
            si = 1.0f - inter / (uni + 1e-6f);
        }
    }
    #pragma unroll
    for (int o = 16; o; o >>= 1) {
        sc += __shfl_down_sync(0xFFFFFFFFu, sc, o);
        ss += __shfl_down_sync(0xFFFFFFFFu, ss, o);
        so += __shfl_down_sync(0xFFFFFFFFu, so, o);
        si += __shfl_down_sync(0xFFFFFFFFu, si, o);
        cf += __shfl_down_sync(0xFFFFFFFFu, cf, o);
    }
    if (lane == 0 && cf != 0.0f) {
        atomicAdd(&g_acc[0], sc);
        atomicAdd(&g_acc[1], ss);
        atomicAdd(&g_acc[2], so);
        atomicAdd(&g_acc[3], si);
        atomicAdd(&g_acc[4], cf);
    }

    // ========== finalize: arrive-only; last arriver writes out =============
    __syncthreads();
    if (tid == 0) {
        __threadfence();
        unsigned a = atomicAdd((unsigned*)&g_bcnt[2], 1u);
        if (a == GBLK - 1) {
            g_bcnt[2] = 0;
            float a0 = atomicAdd(&g_acc[0], 0.0f);
            float a1 = atomicAdd(&g_acc[1], 0.0f);
            float a2 = atomicAdd(&g_acc[2], 0.0f);
            float a3 = atomicAdd(&g_acc[3], 0.0f);
            float a4 = atomicAdd(&g_acc[4], 0.0f);
            float k  = fmaxf(a4, 1.0f);
            out[0] = a0 / (3.0f * k) + 0.5f * (a1 / (3.0f * k) + a2 / k)
                   + 2.0f * (a3 / k);
        }
    }
}

// ---------------- launch ----------------
extern "C" void kernel_launch(void* const* d_in, const int* in_sizes, int n_in,
                              void* d_out, int out_size) {
    const float* pred = (const float*)d_in[0];
    const float* gt   = (const float*)d_in[1];
    int m = in_sizes[0] / 7;
    int n = in_sizes[1] / 7;
    fused_kernel<<<GBLK, TBLK>>>(pred, gt, m, n, (float*)d_out);
}

// round 11
// speedup vs baseline: 1.0262x; 1.0262x over previous
#include <cuda_runtime.h>
#include <cstdint>

#define GRID1   20
#define NCPAD   8192
#define CAP     16             // bucket capacity (overflow P ~ 2e-12)
#define KC      20             // register candidate cap (P(cnt>20) ~ 1e-9)
#define CSTRIDE 32
#define MAXM    8192
#define MAXN    8192
#define GBLK    128
#define TBLK    64
#define OWNER_INIT 0x7FFFFFFF

typedef unsigned long long u64;

// ---------------- device scratch (no allocations allowed) ----------------
__device__ int            g_cellcnt[NCPAD];          // zero-init; phase D re-zeros
__device__ float4         g_bucket[NCPAD * CAP];     // (x,y,z,bitcast id)
__device__ uint4          g_row[MAXM];               // cnt | first 7 sorted candidates
__device__ unsigned short g_sorted[MAXM * CSTRIDE];  // overflow (pos >= 7)
__device__ int            g_owner[MAXN];             // packed (row<<5 | pos)
__device__ float          g_acc[5];
__device__ volatile unsigned g_bcnt[4];              // zero-init; self-resetting
__device__ volatile unsigned g_bgen[4];              // monotonic generation

__device__ __forceinline__ int cell1(float x) {
    int c = (int)floorf(x * 0.2f);
    return min(max(c, 0), GRID1 - 1);
}

// Generation-based grid barrier; all GBLK blocks co-resident (128 <= 148 SMs).
__device__ __forceinline__ void gsync(int k) {
    __syncthreads();
    if (threadIdx.x == 0) {
        unsigned old = g_bgen[k];
        __threadfence();
        unsigned a = atomicAdd((unsigned*)&g_bcnt[k], 1u);
        if (a == GBLK - 1) {
            g_bcnt[k] = 0;
            __threadfence();
            atomicAdd((unsigned*)&g_bgen[k], 1u);
        } else {
            while (g_bgen[k] == old) { }
        }
    }
    __syncthreads();
    __threadfence();
}

// candidate p of a row given its packed uint4; own=true may use L1 (own writes)
__device__ __forceinline__ int cand_at(uint4 rv, int p, int row, bool own) {
    if (p < 7) {
        unsigned w = (p == 0) ? rv.x : (p < 3) ? rv.y : (p < 5) ? rv.z : rv.w;
        int sh = (p == 0) ? 16 : ((p & 1) ? 0 : 16);
        return (int)((w >> sh) & 0xFFFFu);
    }
    const unsigned short* q = &g_sorted[(size_t)row * CSTRIDE + p];
    return own ? (int)*q : (int)__ldcg(q);
}

__device__ __forceinline__ float sl1(float x) {
    float a = fabsf(x);
    return (a < 1.0f) ? 0.5f * a * a : a - 0.5f;
}

__global__ void __launch_bounds__(TBLK)
fused_kernel(const float* __restrict__ pred, const float* __restrict__ gt,
             int m, int n, float* __restrict__ out) {
    int b = blockIdx.x, tid = threadIdx.x;
    int lane = tid & 31;
    int i = b * TBLK + tid;                 // one pred row AND one gt per thread

    // Hoist pred xyz loads: in flight during phase A + barrier.
    float px = 0.f, py = 0.f, pz = 0.f;
    bool rowv = (i < m);
    if (rowv) {
        px = __ldg(&pred[i * 7 + 0]);
        py = __ldg(&pred[i * 7 + 1]);
        pz = __ldg(&pred[i * 7 + 2]);
    }

    // ========== phase A: bucket build + owner/acc init (fully parallel) ====
    float gx = 0.f, gy = 0.f, gz = 0.f;
    if (i < 5) g_acc[i] = 0.0f;
    if (i < n) {
        g_owner[i] = OWNER_INIT;
        const float* g = gt + (size_t)i * 7;
        gx = __ldg(g); gy = __ldg(g + 1); gz = __ldg(g + 2);
        int c = (cell1(gz) * GRID1 + cell1(gy)) * GRID1 + cell1(gx);
        int slot = atomicAdd(&g_cellcnt[c], 1);
        if (slot < CAP)
            g_bucket[c * CAP + slot] = make_float4(gx, gy, gz, __int_as_float(i));
    }
    gsync(0);

    // ========== phase B: query, z-plane batched, register min-sweep ========
    // Per-dim neighborhood [cell1(px-5), cell1(px+5)] spans <=3 consecutive
    // cells and is a superset (monotone f32 ops); exact dsq<25 test ->
    // identical candidate set to brute force. Entry0 loads are speculative
    // (clamped in-bounds; used only when count>0). a[] holds the KC smallest
    // keys (fbits(dsq)<<32 | j) ascending via register min-sweep == exact
    // serial-argmin order (rounds 1-10).
    uint4 rv = make_uint4(0, 0, 0, 0);
    int   cnt = 0;
    if (rowv) {
        u64 a[KC];
        #pragma unroll
        for (int k = 0; k < KC; ++k) a[k] = ~0ull;
        int x0 = cell1(px - 5.0f), x1 = cell1(px + 5.0f);
        int y0 = cell1(py - 5.0f), y1 = cell1(py + 5.0f);
        int z0 = cell1(pz - 5.0f), z1 = cell1(pz + 5.0f);

        for (int zz = z0; zz <= z1; ++zz) {
            int    cc[9], ci[9];
            float4 v0[9];
            #pragma unroll
            for (int dy = 0; dy < 3; ++dy) {
                int yy = y0 + dy;
                #pragma unroll
                for (int dx = 0; dx < 3; ++dx) {
                    int k = dy * 3 + dx;
                    int xx = x0 + dx;
                    bool ok = (yy <= y1) && (xx <= x1);
                    int c = (zz * GRID1 + yy) * GRID1 + xx;
                    c = min(c, NCPAD - 1);           // clamp: always in-bounds
                    ci[k] = c;
                    cc[k] = ok ? __ldg(&g_cellcnt[c]) : 0;
                }
            }
            #pragma unroll
            for (int k = 0; k < 9; ++k) v0[k] = __ldg(&g_bucket[ci[k] * CAP]);

            #pragma unroll
            for (int k = 0; k < 9; ++k) {
                int c2 = min(cc[k], CAP);
                for (int t = 0; t < c2; ++t) {       // c2>1 rare (mean ~1)
                    float4 v = (t == 0) ? v0[k]
                                        : __ldg(&g_bucket[ci[k] * CAP + t]);
                    float dx = px - v.x, dy = py - v.y, dz = pz - v.z;
                    float d = fmaf(dx, dx, fmaf(dy, dy, dz * dz));
                    if (d < 25.0f) {
                        u64 key = ((u64)__float_as_uint(d) << 32)
                                | (unsigned)__float_as_int(v.w);
                        ++cnt;
                        #pragma unroll
                        for (int k2 = 0; k2 < KC; ++k2) {   // register min-sweep
                            u64 mn = min(a[k2], key);
                            key = a[k2] ^ key ^ mn;
                            a[k2] = mn;
                        }
                    }
                }
            }
        }
        cnt = min(cnt, KC);
        unsigned c7[7];
        #pragma unroll
        for (int k = 0; k < 7; ++k)
            c7[k] = (k < cnt) ? (unsigned)(a[k] & 0xFFFFu) : 0u;
        rv.x = (unsigned)cnt | (c7[0] << 16);
        rv.y = c7[1] | (c7[2] << 16);
        rv.z = c7[3] | (c7[4] << 16);
        rv.w = c7[5] | (c7[6] << 16);
        g_row[i] = rv;
        #pragma unroll
        for (int k = 7; k < KC; ++k)
            if (k < cnt)
                g_sorted[(size_t)i * CSTRIDE + k] =
                    (unsigned short)(a[k] & 0xFFFFu);
    }
    __threadfence();   // release g_row/g_sorted before owner atomics

    // ========== phase C: eager-chain matcher with batched peeks ============
    // owner[j] = min packed (row<<5|pos) ever proposed (atomicMin, monotone).
    // Packed lexicographic order == row priority. On displacement, the winner
    // continues the displaced row's walk. NEW: after losing a claim, scan
    // ahead with batched __ldcg peeks (4/wave, independent) — a peeked value
    // < my packed licenses a skip permanently (monotonicity: current <=
    // stale < mine), identical to the verified advance rule; the atomicMin
    // still arbitrates every actual claim. Fixed point == sequential greedy
    // (rounds 3-10).
    if (rowv) {
        int cur = i, p = 0, ccnt = cnt;
        uint4 crv = rv;
        bool own = true;
        while (p < ccnt) {
            int j = cand_at(crv, p, cur, own);
            int my = (cur << 5) | p;
            int old = atomicMin(&g_owner[j], my);
            if (old >= my) {
                if (old == OWNER_INIT) break;        // parked empty slot: done
                cur = old >> 5;                      // continue displaced row
                p = (old & 31) + 1;
                crv = __ldcg(&g_row[cur]);
                ccnt = (int)(crv.x & 0xFFFFu);
                own = false;
                continue;
            }
            // lost at p: peek-batched scan for the next winnable position
            ++p;
            while (p < ccnt) {
                int np = min(ccnt - p, 4);
                int ov[4];
                #pragma unroll
                for (int q = 0; q < 4; ++q)
                    if (q < np)
                        ov[q] = __ldcg(&g_owner[cand_at(crv, p + q, cur, own)]);
                int q = 0;
                while (q < np && ov[q] < ((cur << 5) | (p + q))) ++q;
                p += q;
                if (q < np) break;                   // winnable: atomic at p
            }
        }
    }
    gsync(1);

    // ========== phase D: gt-side loss (owner[j]>>5 IS the matched row) =====
    // At fixed point each row owns <=1 gt (a parked entry is only replaced by
    // a strictly smaller packed value, which resumes that row's walk past it),
    // so iterating gts enumerates exactly the matched pairs, once each.
    if (i < NCPAD) g_cellcnt[i] = 0;             // zero-state for next replay

    float sc = 0.f, ss = 0.f, so = 0.f, si = 0.f, cf = 0.f;
    if (i < n) {
        int v = __ldcg(&g_owner[i]);             // atomics live in L2
        if (v != OWNER_INIT) {
            int r = v >> 5;                      // matched pred row
            cf = 1.0f;
            const float* pp = pred + (size_t)r * 7;
            const float* gg = gt + (size_t)i * 7;
            float p0 = __ldg(pp),     p1 = __ldg(pp + 1), p2 = __ldg(pp + 2);
            float p3 = __ldg(pp + 3), p4 = __ldg(pp + 4), p5 = __ldg(pp + 5);
            float p6 = __ldg(pp + 6);
            float g3 = __ldg(gg + 3), g4 = __ldg(gg + 4), g5 = __ldg(gg + 5);
            float g6 = __ldg(gg + 6);
            sc = sl1(p0 - gx) + sl1(p1 - gy) + sl1(p2 - gz);
            ss = sl1(p3 - g3) + sl1(p4 - g4) + sl1(p5 - g5);
            float dth = p6 - g6;
            dth = fmaf(-rintf(dth * 0.15915494309f), 6.283185307f, dth);
            so = sl1(dth);                       // sl1(|.|) symmetric: wrap dir irrelevant
            float iw = fminf(p0 + p3 * 0.5f, gx + g3 * 0.5f)
                     - fmaxf(p0 - p3 * 0.5f, gx - g3 * 0.5f);
            iw = fmaxf(iw, 0.0f);
            float ih = fminf(p1 + p4 * 0.5f, gy + g4 * 0.5f)
                     - fmaxf(p1 - p4 * 0.5f, gy - g4 * 0.5f);
            ih = fmaxf(ih, 0.0f);
            float inter = iw * ih;
            float uni = p3 * p4 + g3 * g4 - inter;
            si = 1.0f - inter / (uni + 1e-6f);
        }
    }
    #pragma unroll
    for (int o = 16; o; o >>= 1) {
        sc += __shfl_down_sync(0xFFFFFFFFu, sc, o);
        ss += __shfl_down_sync(0xFFFFFFFFu, ss, o);
        so += __shfl_down_sync(0xFFFFFFFFu, so, o);
        si += __shfl_down_sync(0xFFFFFFFFu, si, o);
        cf += __shfl_down_sync(0xFFFFFFFFu, cf, o);
    }
    if (lane == 0 && cf != 0.0f) {
        atomicAdd(&g_acc[0], sc);
        atomicAdd(&g_acc[1], ss);
        atomicAdd(&g_acc[2], so);
        atomicAdd(&g_acc[3], si);
        atomicAdd(&g_acc[4], cf);
    }

    // ========== finalize: arrive-only; last arriver writes out =============
    __syncthreads();
    if (tid == 0) {
        __threadfence();
        unsigned a = atomicAdd((unsigned*)&g_bcnt[2], 1u);
        if (a == GBLK - 1) {
            g_bcnt[2] = 0;
            float a0 = atomicAdd(&g_acc[0], 0.0f);
            float a1 = atomicAdd(&g_acc[1], 0.0f);
            float a2 = atomicAdd(&g_acc[2], 0.0f);
            float a3 = atomicAdd(&g_acc[3], 0.0f);
            float a4 = atomicAdd(&g_acc[4], 0.0f);
            float k  = fmaxf(a4, 1.0f);
            out[0] = a0 / (3.0f * k) + 0.5f * (a1 / (3.0f * k) + a2 / k)
                   + 2.0f * (a3 / k);
        }
    }
}

// ---------------- launch ----------------
extern "C" void kernel_launch(void* const* d_in, const int* in_sizes, int n_in,
                              void* d_out, int out_size) {
    const float* pred = (const float*)d_in[0];
    const float* gt   = (const float*)d_in[1];
    int m = in_sizes[0] / 7;
    int n = in_sizes[1] / 7;
    fused_kernel<<<GBLK, TBLK>>>(pred, gt, m, n, (float*)d_out);
}